// round 4
// baseline (speedup 1.0000x reference)
#include <cuda_runtime.h>
#include <cstdint>
#include <cstddef>
#include <utility>

// ============================================================================
// Compile-time reimplementation of the reference build_metadata():
// real Wigner-3j (e3nn convention) -> sparse (mu1, mu2, i3_local, cg) lists,
// grouped by path, all constexpr. Device code NEVER touches the META struct
// directly (that odr-uses a host constexpr object); instead every value is
// exposed as a scalar `static constexpr` member of a template struct, whose
// initializer is evaluated by the frontend at instantiation time.
// ============================================================================

namespace cgmeta {

constexpr int LMAX = 3;
constexpr int MAXNNZ = 1024;
constexpr int MAXPATH = 32;

// factorials up to 10! (max arg: j1+j2+j3+1 = 10)
constexpr double FACT[11] = {1.0, 1.0, 2.0, 6.0, 24.0, 120.0, 720.0,
                             5040.0, 40320.0, 362880.0, 3628800.0};

constexpr double csqrt(double x) {
    if (x <= 0.0) return 0.0;
    double g = (x > 1.0) ? x : 1.0;
    for (int i = 0; i < 64; ++i) g = 0.5 * (g + x / g);
    return g;
}

constexpr int imax2(int a, int b) { return a > b ? a : b; }
constexpr int imin2(int a, int b) { return a < b ? a : b; }

struct C2 { double r, i; };
constexpr C2 cmul(C2 a, C2 b) { return C2{a.r * b.r - a.i * b.i, a.r * b.i + a.i * b.r}; }
constexpr C2 cadd(C2 a, C2 b) { return C2{a.r + b.r, a.i + b.i}; }

// SU(2) Clebsch-Gordan coefficient, exactly mirroring the reference _cg_coef
constexpr double cg_coef(int j1, int m1, int j2, int m2, int j3, int m3) {
    if (m3 != m1 + m2) return 0.0;
    int vmin = imax2(imax2(-j1 + j2 + m3, -j1 + m1), 0);
    int vmax = imin2(imin2(j2 + j3 + m1, j3 - j1 + j2), j3 + m3);
    double C = csqrt((2.0 * j3 + 1.0)
                     * FACT[j3 + j1 - j2] * FACT[j3 - j1 + j2] * FACT[j1 + j2 - j3]
                     / FACT[j1 + j2 + j3 + 1]
                     * FACT[j3 + m3] * FACT[j3 - m3]
                     / (FACT[j1 + m1] * FACT[j1 - m1] * FACT[j2 + m2] * FACT[j2 - m2]));
    double S = 0.0;
    for (int v = vmin; v <= vmax; ++v) {
        double sgn = ((v + j2 + m2) % 2) ? -1.0 : 1.0;
        S += sgn * FACT[j2 + j3 + m1 - v] * FACT[j1 - m1 + v]
             / (FACT[v] * FACT[j3 - j1 + j2 - v] * FACT[j3 + m3 - v] * FACT[v + j1 - j2 - m3]);
    }
    return C * S;
}

// change-of-basis matrix q(l): real -> complex spherical harmonics (e3nn)
struct QM { C2 q[7][7]; };
constexpr QM qmat(int l) {
    QM Q{};
    double s = 1.0 / csqrt(2.0);
    for (int m = -l; m < 0; ++m) {
        Q.q[l + m][l - m] = C2{s, 0.0};      // column l + |m|
        Q.q[l + m][l + m] = C2{0.0, -s};     // column l - |m|
    }
    Q.q[l][l] = C2{1.0, 0.0};
    for (int m = 1; m <= l; ++m) {
        double sg = (m % 2) ? -1.0 : 1.0;
        Q.q[l + m][l + m] = C2{sg * s, 0.0};
        Q.q[l + m][l - m] = C2{0.0, sg * s};
    }
    // multiply by (-i)^l
    C2 ph = (l % 4 == 0) ? C2{1, 0} : (l % 4 == 1) ? C2{0, -1}
          : (l % 4 == 2) ? C2{-1, 0} : C2{0, 1};
    for (int a = 0; a < 2 * l + 1; ++a)
        for (int b = 0; b < 2 * l + 1; ++b)
            Q.q[a][b] = cmul(ph, Q.q[a][b]);
    return Q;
}

// real Wigner-3j tensor, Frobenius-normalized to 1
struct W3J { double v[7][7][7]; };
constexpr W3J wigner3j(int l1, int l2, int l3) {
    int d1 = 2 * l1 + 1, d2 = 2 * l2 + 1, d3 = 2 * l3 + 1;
    double Csu[7][7][7] = {};
    for (int m1 = -l1; m1 <= l1; ++m1)
        for (int m2 = -l2; m2 <= l2; ++m2) {
            int m3 = m1 + m2;
            if (m3 >= -l3 && m3 <= l3)
                Csu[l1 + m1][l2 + m2][l3 + m3] = cg_coef(l1, m1, l2, m2, l3, m3);
        }
    QM Q1 = qmat(l1), Q2 = qmat(l2), Q3 = qmat(l3);
    // A[j][k][n] = sum_i Q1[i][j] * Csu[i][k][n]
    C2 A[7][7][7] = {};
    for (int j = 0; j < d1; ++j)
        for (int k = 0; k < d2; ++k)
            for (int n = 0; n < d3; ++n) {
                C2 s{0, 0};
                for (int i = 0; i < d1; ++i) {
                    double c = Csu[i][k][n];
                    s.r += Q1.q[i][j].r * c;
                    s.i += Q1.q[i][j].i * c;
                }
                A[j][k][n] = s;
            }
    // B[j][l][n] = sum_k Q2[k][l] * A[j][k][n]
    C2 B[7][7][7] = {};
    for (int j = 0; j < d1; ++j)
        for (int l = 0; l < d2; ++l)
            for (int n = 0; n < d3; ++n) {
                C2 s{0, 0};
                for (int k = 0; k < d2; ++k) s = cadd(s, cmul(Q2.q[k][l], A[j][k][n]));
                B[j][l][n] = s;
            }
    // R[j][l][m] = Re( sum_n conj(Q3[n][m]) * B[j][l][n] )
    W3J R{};
    double norm2 = 0.0;
    for (int j = 0; j < d1; ++j)
        for (int l = 0; l < d2; ++l)
            for (int m = 0; m < d3; ++m) {
                C2 s{0, 0};
                for (int n = 0; n < d3; ++n) {
                    C2 qc{Q3.q[n][m].r, -Q3.q[n][m].i};
                    s = cadd(s, cmul(qc, B[j][l][n]));
                }
                R.v[j][l][m] = s.r;
                norm2 += s.r * s.r;
            }
    double inv = 1.0 / csqrt(norm2);
    for (int j = 0; j < d1; ++j)
        for (int l = 0; l < d2; ++l)
            for (int m = 0; m < d3; ++m)
                R.v[j][l][m] *= inv;
    return R;
}

struct Meta {
    int npaths;
    int nnz;
    int out_dim;
    int pstart[MAXPATH], pcount[MAXPATH], pooff[MAXPATH], podim[MAXPATH];
    int e1[MAXNNZ];      // mu1 (global row in x, 0..15)
    int e2[MAXNNZ];      // mu2 (global row in y, 0..15)
    int e3[MAXNNZ];      // local i3 within path (0..2*l3)
    float w[MAXNNZ];     // cg * sqrt(2*l3+1)
};

constexpr Meta build_meta() {
    Meta M{};
    int out_dim = 0, off1 = 0, nnz = 0, np = 0;
    for (int l1 = 0; l1 <= LMAX; ++l1) {
        int p1 = (l1 % 2) ? -1 : 1;
        int off2 = 0;
        for (int l2 = 0; l2 <= LMAX; ++l2) {
            int p2 = (l2 % 2) ? -1 : 1;
            int lo = (l1 > l2) ? (l1 - l2) : (l2 - l1);
            for (int l3 = lo; l3 <= l1 + l2; ++l3) {
                int p3 = (l3 % 2) ? -1 : 1;
                if (l3 <= LMAX && p1 * p2 == p3) {
                    W3J R = wigner3j(l1, l2, l3);
                    double pw = csqrt(2.0 * l3 + 1.0);
                    M.pstart[np] = nnz;
                    M.pooff[np] = out_dim;
                    M.podim[np] = 2 * l3 + 1;
                    int cnt = 0;
                    for (int a = 0; a < 2 * l1 + 1; ++a)
                        for (int b = 0; b < 2 * l2 + 1; ++b)
                            for (int c = 0; c < 2 * l3 + 1; ++c) {
                                double val = R.v[a][b][c] * pw;
                                double av = val < 0 ? -val : val;
                                if (av > 1e-12) {
                                    M.e1[nnz] = a + off1;
                                    M.e2[nnz] = b + off2;
                                    M.e3[nnz] = c;
                                    M.w[nnz] = (float)val;
                                    ++nnz;
                                    ++cnt;
                                }
                            }
                    M.pcount[np] = cnt;
                    ++np;
                    out_dim += 2 * l3 + 1;
                }
            }
            off2 += 2 * l2 + 1;
        }
        off1 += 2 * l1 + 1;
    }
    M.npaths = np;
    M.nnz = nnz;
    M.out_dim = out_dim;
    return M;
}

constexpr Meta META = build_meta();
static_assert(META.out_dim == 99, "output dim mismatch");
static_assert(META.nnz <= MAXNNZ, "nnz overflow");

// --- scalar constexpr exports (legal in device code; META itself is not) ---
constexpr int NPATHS = META.npaths;

// Per-entry scalars: initializers are constant expressions evaluated at
// template instantiation by the frontend; device code only sees literals.
template <int I>
struct Ent {
    static constexpr int   i1 = META.e1[I];
    static constexpr int   i2 = META.e2[I];
    static constexpr int   i3 = META.e3[I];
    static constexpr float w  = META.w[I];
};

// Per-path scalars.
template <int P>
struct Path {
    static constexpr int base = META.pstart[P];
    static constexpr int cnt  = META.pcount[P];
    static constexpr int ooff = META.pooff[P];
    static constexpr int odim = META.podim[P];
};

} // namespace cgmeta

// ============================================================================
// Kernel: one block per edge, one thread per channel.
// x,y rows live in registers (static indices), CG weights are FFMA
// immediates, outputs stream directly to GMEM with streaming stores.
// ============================================================================

using cgmeta::Ent;
using cgmeta::Path;
using cgmeta::NPATHS;

template <int Base, size_t... Es>
__device__ __forceinline__ void accum_entries(float (&acc)[7],
                                              const float (&xs)[16],
                                              const float (&ys)[16],
                                              std::index_sequence<Es...>) {
    ((acc[Ent<Base + (int)Es>::i3] +=
          Ent<Base + (int)Es>::w * (xs[Ent<Base + (int)Es>::i1] * ys[Ent<Base + (int)Es>::i2])),
     ...);
}

template <int Ooff, size_t... Ks>
__device__ __forceinline__ void store_rows(const float (&acc)[7], float* __restrict__ op,
                                           std::index_sequence<Ks...>) {
    (__stcs(op + (size_t)(Ooff + (int)Ks) * 128, acc[(int)Ks]), ...);
}

template <int P>
__device__ __forceinline__ void do_path(const float (&xs)[16], const float (&ys)[16],
                                        float* __restrict__ op) {
    float acc[7] = {0.f, 0.f, 0.f, 0.f, 0.f, 0.f, 0.f};
    accum_entries<Path<P>::base>(acc, xs, ys,
                                 std::make_index_sequence<(size_t)Path<P>::cnt>{});
    store_rows<Path<P>::ooff>(acc, op,
                              std::make_index_sequence<(size_t)Path<P>::odim>{});
}

template <size_t... Ps>
__device__ __forceinline__ void all_paths(const float (&xs)[16], const float (&ys)[16],
                                          float* __restrict__ op, std::index_sequence<Ps...>) {
    (do_path<(int)Ps>(xs, ys, op), ...);
}

__global__ void __launch_bounds__(128)
tp_kernel(const float* __restrict__ x, const float* __restrict__ y,
          float* __restrict__ out) {
    const int n = blockIdx.x;
    const int c = threadIdx.x;

    const float* xp = x + (size_t)n * (16 * 128) + c;
    const float* yp = y + (size_t)n * (16 * 128) + c;

    float xs[16], ys[16];
#pragma unroll
    for (int m = 0; m < 16; ++m) {
        xs[m] = __ldg(xp + m * 128);
        ys[m] = __ldg(yp + m * 128);
    }

    float* op = out + (size_t)n * (99 * 128) + c;
    all_paths(xs, ys, op, std::make_index_sequence<(size_t)NPATHS>{});
}

extern "C" void kernel_launch(void* const* d_in, const int* in_sizes, int n_in,
                              void* d_out, int out_size) {
    const float* x = (const float*)d_in[0];
    const float* y = (const float*)d_in[1];
    float* out = (float*)d_out;

    const int n_edges = in_sizes[0] / (16 * 128);
    tp_kernel<<<n_edges, 128>>>(x, y, out);
}